// round 9
// baseline (speedup 1.0000x reference)
#include <cuda_runtime.h>
#include <math.h>

#define HW (768 * 768)
#define HW4 (HW / 4)
#define SPTS 8192
#define NCHUNK 16
#define CHUNK 512                // dst points per chamfer block
#define SRCB 512                 // src points per chamfer block (256 thr x 2)
#define NCHAM 512                // 2 dir * 16 srcblk * 16 chunk
#define NMAIN 592
#define NFUSE (NCHAM + NMAIN)    // 1104
#define NP2 592

// 0 mask,1 nsq,2 den,3 num,4 bce,5 eik,6 sdf,7 con,8 vis,9 derr,10 pc_xy,11 pc_yx
__device__ double g_acc[12];
__device__ unsigned int g_min[2 * SPTS];   // per-source-point min dist^2 (uint-ordered floats >= 0)

typedef unsigned long long u64;

__device__ __forceinline__ u64 fma2(u64 a, u64 b, u64 c) {
    u64 d; asm("fma.rn.f32x2 %0,%1,%2,%3;" : "=l"(d) : "l"(a), "l"(b), "l"(c)); return d;
}
__device__ __forceinline__ u64 pk2(float lo, float hi) {
    u64 d; asm("mov.b64 %0,{%1,%2};" : "=l"(d) : "f"(lo), "f"(hi)); return d;
}
__device__ __forceinline__ void upk(u64 v, float& lo, float& hi) {
    asm("mov.b64 {%0,%1},%2;" : "=f"(lo), "=f"(hi) : "l"(v));
}
__device__ __forceinline__ float warpSum(float v) {
    #pragma unroll
    for (int o = 16; o; o >>= 1) v += __shfl_xor_sync(0xffffffffu, v, o);
    return v;
}

// ---------------------------------------------------------------------------
// Init: zero accumulators, set g_min to +inf
// ---------------------------------------------------------------------------
__global__ void kInit() {
    const int t = blockIdx.x * 256 + threadIdx.x;
    if (t < 12) g_acc[t] = 0.0;
    if (t < 2 * SPTS) g_min[t] = 0x7F800000u;   // +inf
}

// ---------------------------------------------------------------------------
// Fused kernel: interleaved chamfer blocks (FMA-bound) + streaming blocks
// (HBM-bound) so both kinds co-reside per SM and overlap.
// role: bid < 2*NCHAM -> even=cham, odd=main ; bid >= 2*NCHAM -> main
// ---------------------------------------------------------------------------
__global__ void __launch_bounds__(256) kFuse(
    const float* __restrict__ npred, const float* __restrict__ ngt,
    const float* __restrict__ dpred, const float* __restrict__ dgt,
    const float* __restrict__ X,     const float* __restrict__ Y,
    const float* __restrict__ mask,  const float* __restrict__ comp,
    const float* __restrict__ grad,  const float* __restrict__ sdf,
    const float* __restrict__ nwa,   const float* __restrict__ vis,
    const float* __restrict__ w, int N, int P, int C)
{
    __shared__ __align__(16) float sh0[CHUNK];
    __shared__ __align__(16) float sh1[CHUNK];
    __shared__ __align__(16) float sh2[CHUNK];
    __shared__ __align__(16) float shw[CHUNK];

    const int bid = blockIdx.x;
    const bool is_cham = (bid < 2 * NCHAM) && ((bid & 1) == 0);

    if (is_cham) {
        // ---------------- chamfer: 512 src (2/thread) x 512 dst ------------
        const int cb = bid >> 1;             // 0..511
        const int dir = cb >> 8;             // 256 blocks per direction
        const int rem = cb & 255;
        const int srcblk = rem >> 4;         // 16 src-blocks of 512
        const int chunk = rem & 15;          // 16 dst-chunks of 512
        const float* __restrict__ src = dir ? Y : X;
        const float* __restrict__ dst = dir ? X : Y;

        const int base = chunk * CHUNK;
        for (int i = threadIdx.x; i < CHUNK; i += 256) {
            float y0 = dst[3 * (base + i) + 0];
            float y1 = dst[3 * (base + i) + 1];
            float y2 = dst[3 * (base + i) + 2];
            sh0[i] = y0; sh1[i] = y1; sh2[i] = y2;
            shw[i] = fmaf(y0, y0, fmaf(y1, y1, y2 * y2));
        }
        __syncthreads();

        u64 A0[2], A1[2], A2[2];
        float XX[2], M0[2], M1[2];
        #pragma unroll
        for (int r = 0; r < 2; r++) {
            int s = srcblk * SRCB + r * 256 + threadIdx.x;
            float x0 = src[3 * s], x1 = src[3 * s + 1], x2 = src[3 * s + 2];
            A0[r] = pk2(-2.0f * x0, -2.0f * x0);
            A1[r] = pk2(-2.0f * x1, -2.0f * x1);
            A2[r] = pk2(-2.0f * x2, -2.0f * x2);
            XX[r] = fmaf(x0, x0, fmaf(x1, x1, x2 * x2));
            M0[r] = 3.0e38f; M1[r] = 3.0e38f;
        }

        const u64* __restrict__ q0 = (const u64*)sh0;
        const u64* __restrict__ q1 = (const u64*)sh1;
        const u64* __restrict__ q2 = (const u64*)sh2;
        const u64* __restrict__ qw = (const u64*)shw;

        #pragma unroll 4
        for (int i = 0; i < CHUNK / 4; i++) {
            u64 b0a = q0[2 * i], b0b = q0[2 * i + 1];
            u64 b1a = q1[2 * i], b1b = q1[2 * i + 1];
            u64 b2a = q2[2 * i], b2b = q2[2 * i + 1];
            u64 wa  = qw[2 * i], wb  = qw[2 * i + 1];
            #pragma unroll
            for (int r = 0; r < 2; r++) {
                u64 sA = fma2(A0[r], b0a, fma2(A1[r], b1a, fma2(A2[r], b2a, wa)));
                u64 sB = fma2(A0[r], b0b, fma2(A1[r], b1b, fma2(A2[r], b2b, wb)));
                float lo, hi;
                upk(sA, lo, hi); M0[r] = fminf(M0[r], lo); M1[r] = fminf(M1[r], hi);
                upk(sB, lo, hi); M0[r] = fminf(M0[r], lo); M1[r] = fminf(M1[r], hi);
            }
        }
        #pragma unroll
        for (int r = 0; r < 2; r++) {
            int s = srcblk * SRCB + r * 256 + threadIdx.x;
            float v = fmaxf(XX[r] + fminf(M0[r], M1[r]), 0.0f);   // >=0 so uint order == float order
            atomicMin(&g_min[(dir << 13) + s], __float_as_uint(v));
        }
        return;
    }

    // ------------------ streaming reductions -------------------------------
    const int mblk = (bid < 2 * NCHAM) ? (bid >> 1) : (NCHAM + bid - 2 * NCHAM);
    const int tid = mblk * 256 + threadIdx.x;
    const int stride = NMAIN * 256;

    float s_mask = 0.f, s_nsq = 0.f, s_den = 0.f, s_num = 0.f, s_bce = 0.f;
    const float4* __restrict__ mk4 = (const float4*)mask;
    const float4* __restrict__ cp4 = (const float4*)comp;
    const float4* __restrict__ dg4 = (const float4*)dgt;
    const float4* __restrict__ dp4 = (const float4*)dpred;
    const float4* __restrict__ np4 = (const float4*)npred;
    const float4* __restrict__ ng4 = (const float4*)ngt;

    for (int g = tid; g < HW4; g += stride) {
        float4 mk = mk4[g];
        float m0 = mk.x > 0.5f ? 1.f : 0.f;
        float m1 = mk.y > 0.5f ? 1.f : 0.f;
        float m2 = mk.z > 0.5f ? 1.f : 0.f;
        float m3 = mk.w > 0.5f ? 1.f : 0.f;
        s_mask += (m0 + m1) + (m2 + m3);

        float4 A0 = np4[3 * g], A1 = np4[3 * g + 1], A2 = np4[3 * g + 2];
        float4 B0 = ng4[3 * g], B1 = ng4[3 * g + 1], B2 = ng4[3 * g + 2];
        float d0x = A0.x - B0.x, d0y = A0.y - B0.y, d0z = A0.z - B0.z;
        float d1x = A0.w - B0.w, d1y = A1.x - B1.x, d1z = A1.y - B1.y;
        float d2x = A1.z - B1.z, d2y = A1.w - B1.w, d2z = A2.x - B2.x;
        float d3x = A2.y - B2.y, d3y = A2.z - B2.z, d3z = A2.w - B2.w;
        s_nsq += m0 * fmaf(d0x, d0x, fmaf(d0y, d0y, d0z * d0z));
        s_nsq += m1 * fmaf(d1x, d1x, fmaf(d1y, d1y, d1z * d1z));
        s_nsq += m2 * fmaf(d2x, d2x, fmaf(d2y, d2y, d2z * d2z));
        s_nsq += m3 * fmaf(d3x, d3x, fmaf(d3y, d3y, d3z * d3z));

        float4 dg = dg4[g], dp = dp4[g];
        float vg0 = dg.x * m0, vg1 = dg.y * m1, vg2 = dg.z * m2, vg3 = dg.w * m3;
        float vp0 = dp.x * m0, vp1 = dp.y * m1, vp2 = dp.z * m2, vp3 = dp.w * m3;
        s_den = fmaf(vg0, vg0, fmaf(vg1, vg1, fmaf(vg2, vg2, fmaf(vg3, vg3, s_den))));
        s_num = fmaf(vg0, vp0, fmaf(vg1, vp1, fmaf(vg2, vp2, fmaf(vg3, vp3, s_num))));

        float4 c = cp4[g];
        float c0 = fminf(fmaxf(c.x, 1e-5f), 1.0f - 1e-5f);
        float c1 = fminf(fmaxf(c.y, 1e-5f), 1.0f - 1e-5f);
        float c2 = fminf(fmaxf(c.z, 1e-5f), 1.0f - 1e-5f);
        float c3 = fminf(fmaxf(c.w, 1e-5f), 1.0f - 1e-5f);
        s_bce -= m0 * __logf(c0) + (1.0f - m0) * __logf(1.0f - c0);
        s_bce -= m1 * __logf(c1) + (1.0f - m1) * __logf(1.0f - c1);
        s_bce -= m2 * __logf(c2) + (1.0f - m2) * __logf(1.0f - c2);
        s_bce -= m3 * __logf(c3) + (1.0f - m3) * __logf(1.0f - c3);
    }

    float s_eik = 0.f, s_sdf = 0.f;
    const float4* __restrict__ gr4 = (const float4*)grad;
    const float4* __restrict__ sd4 = (const float4*)sdf;
    const int N4 = N / 4;
    for (int g = tid; g < N4; g += stride) {
        float4 G0 = gr4[3 * g], G1 = gr4[3 * g + 1], G2 = gr4[3 * g + 2];
        float n0 = sqrtf(fmaf(G0.x, G0.x, fmaf(G0.y, G0.y, G0.z * G0.z))) - 1.0f;
        float n1 = sqrtf(fmaf(G0.w, G0.w, fmaf(G1.x, G1.x, G1.y * G1.y))) - 1.0f;
        float n2 = sqrtf(fmaf(G1.z, G1.z, fmaf(G1.w, G1.w, G2.x * G2.x))) - 1.0f;
        float n3 = sqrtf(fmaf(G2.y, G2.y, fmaf(G2.z, G2.z, G2.w * G2.w))) - 1.0f;
        s_eik += fmaf(n0, n0, fmaf(n1, n1, fmaf(n2, n2, n3 * n3)));
        float4 s = sd4[g];
        s_sdf += fabsf(s.x) + fabsf(s.y) + fabsf(s.z) + fabsf(s.w);
    }
    for (int i = N4 * 4 + tid; i < N; i += stride) {
        float g0 = grad[3 * i], g1 = grad[3 * i + 1], g2 = grad[3 * i + 2];
        float d = sqrtf(fmaf(g0, g0, fmaf(g1, g1, g2 * g2))) - 1.0f;
        s_eik = fmaf(d, d, s_eik);
        s_sdf += fabsf(sdf[i]);
    }

    float s_con = 0.f, s_vis = 0.f;
    if (C == 4) {
        const float4* __restrict__ nw4 = (const float4*)nwa;
        const float4* __restrict__ vi4 = (const float4*)vis;
        for (int p = tid; p < P; p += stride) {
            float4 P0 = nw4[3 * p], P1 = nw4[3 * p + 1], P2 = nw4[3 * p + 2];
            float4 V = vi4[p];
            float wp = w[p];
            float dx, dy, dz, mse, vv;
            dx = P0.x - P0.w; dy = P0.y - P1.x; dz = P0.z - P1.y;
            mse = fmaf(dx, dx, fmaf(dy, dy, dz * dz)); vv = V.x * V.y;
            s_vis += vv; s_con = fmaf(mse * vv, wp, s_con);
            dx = P0.w - P1.z; dy = P1.x - P1.w; dz = P1.y - P2.x;
            mse = fmaf(dx, dx, fmaf(dy, dy, dz * dz)); vv = V.y * V.z;
            s_vis += vv; s_con = fmaf(mse * vv, wp, s_con);
            dx = P1.z - P2.y; dy = P1.w - P2.z; dz = P2.x - P2.w;
            mse = fmaf(dx, dx, fmaf(dy, dy, dz * dz)); vv = V.z * V.w;
            s_vis += vv; s_con = fmaf(mse * vv, wp, s_con);
        }
    } else {
        for (int p = tid; p < P; p += stride) {
            float wp = w[p];
            const float* np_ = nwa + (size_t)p * C * 3;
            const float* vp_ = vis + (size_t)p * C;
            float px = np_[0], py = np_[1], pz = np_[2], pv = vp_[0];
            for (int i = 1; i < C; i++) {
                float cx = np_[3 * i], cy = np_[3 * i + 1], cz = np_[3 * i + 2];
                float cv = vp_[i];
                float dx = px - cx, dy = py - cy, dz = pz - cz;
                float mse = fmaf(dx, dx, fmaf(dy, dy, dz * dz));
                float vv = pv * cv;
                s_vis += vv;
                s_con = fmaf(mse * vv, wp, s_con);
                px = cx; py = cy; pz = cz; pv = cv;
            }
        }
    }

    __shared__ float shred[9];
    if (threadIdx.x < 9) shred[threadIdx.x] = 0.f;
    __syncthreads();
    float vals[9] = {s_mask, s_nsq, s_den, s_num, s_bce, s_eik, s_sdf, s_con, s_vis};
    #pragma unroll
    for (int k = 0; k < 9; k++) {
        float r = warpSum(vals[k]);
        if ((threadIdx.x & 31) == 0) atomicAdd(&shred[k], r);
    }
    __syncthreads();
    if (threadIdx.x < 9) atomicAdd(&g_acc[threadIdx.x], (double)shred[threadIdx.x]);
}

// ---------------------------------------------------------------------------
// Pass 2: depth |vg*scale - vp| + chamfer sqrt-sum over g_min (64KB)
// ---------------------------------------------------------------------------
__global__ void __launch_bounds__(256) kP2(
    const float* __restrict__ dpred, const float* __restrict__ dgt,
    const float* __restrict__ mask)
{
    const float den = (float)g_acc[2];
    const float num = (float)g_acc[3];
    float scale = num / den;
    if (!isfinite(scale)) scale = 1.0f;

    const int tid = blockIdx.x * 256 + threadIdx.x;
    const int stride = NP2 * 256;

    const float4* __restrict__ mk4 = (const float4*)mask;
    const float4* __restrict__ dg4 = (const float4*)dgt;
    const float4* __restrict__ dp4 = (const float4*)dpred;

    float s_derr = 0.f;
    for (int g = tid; g < HW4; g += stride) {
        float4 mk = mk4[g];
        float4 dg = dg4[g], dp = dp4[g];
        float m0 = mk.x > 0.5f ? 1.f : 0.f;
        float m1 = mk.y > 0.5f ? 1.f : 0.f;
        float m2 = mk.z > 0.5f ? 1.f : 0.f;
        float m3 = mk.w > 0.5f ? 1.f : 0.f;
        s_derr += fabsf(fmaf(dg.x * m0, scale, -dp.x * m0));
        s_derr += fabsf(fmaf(dg.y * m1, scale, -dp.y * m1));
        s_derr += fabsf(fmaf(dg.z * m2, scale, -dp.z * m2));
        s_derr += fabsf(fmaf(dg.w * m3, scale, -dp.w * m3));
    }

    float s0 = 0.f, s1 = 0.f;
    for (int s = tid; s < 2 * SPTS; s += stride) {
        float d = sqrtf(__uint_as_float(g_min[s]));
        if (s < SPTS) s0 += d; else s1 += d;
    }

    __shared__ float shred[3];
    if (threadIdx.x < 3) shred[threadIdx.x] = 0.f;
    __syncthreads();
    float vals[3] = {s_derr, s0, s1};
    #pragma unroll
    for (int k = 0; k < 3; k++) {
        float r = warpSum(vals[k]);
        if ((threadIdx.x & 31) == 0) atomicAdd(&shred[k], r);
    }
    __syncthreads();
    if (threadIdx.x < 3) atomicAdd(&g_acc[9 + threadIdx.x], (double)shred[threadIdx.x]);
}

// ---------------------------------------------------------------------------
// Final combine: single thread, 12 double reads
// ---------------------------------------------------------------------------
__global__ void kFin(float* __restrict__ out, int out_size, int N)
{
    double mask_sum = g_acc[0] + 1e-5;
    double normal_loss = g_acc[1] / mask_sum;
    double depth_loss = g_acc[9] / (mask_sum + 1e-8);
    if (g_acc[2] < 1e-10) depth_loss = 0.0;
    if (!isfinite(depth_loss)) depth_loss = 0.0;
    double pc = (g_acc[10] + g_acc[11]) / (double)SPTS;
    double bce = g_acc[4] / (double)HW;
    double eik = g_acc[5] / (double)N;
    double sdfl = g_acc[6] / (double)N;
    double con = (g_acc[8] > 0.0) ? g_acc[7] / g_acc[8] : 0.0;
    float loss = (float)(normal_loss + depth_loss + pc + bce + eik + sdfl + con);
    for (int i = 0; i < out_size; i++) out[i] = loss;
}

extern "C" void kernel_launch(void* const* d_in, const int* in_sizes, int n_in,
                              void* d_out, int out_size)
{
    const float* npred = (const float*)d_in[0];
    const float* ngt   = (const float*)d_in[1];
    const float* dpred = (const float*)d_in[2];
    const float* dgt   = (const float*)d_in[3];
    const float* X     = (const float*)d_in[4];
    const float* Y     = (const float*)d_in[5];
    const float* mask  = (const float*)d_in[6];
    const float* comp  = (const float*)d_in[7];
    const float* grad  = (const float*)d_in[8];
    const float* sdf   = (const float*)d_in[9];
    const float* nwa   = (const float*)d_in[10];
    const float* vis   = (const float*)d_in[11];
    const float* w     = (const float*)d_in[12];

    int N = in_sizes[9];
    int P = in_sizes[12];
    int C = in_sizes[11] / P;

    kInit<<<64, 256>>>();
    kFuse<<<NFUSE, 256>>>(npred, ngt, dpred, dgt, X, Y, mask, comp, grad, sdf, nwa, vis, w, N, P, C);
    kP2<<<NP2, 256>>>(dpred, dgt, mask);
    kFin<<<1, 1>>>((float*)d_out, out_size, N);
}

// round 12
// speedup vs baseline: 1.6041x; 1.6041x over previous
#include <cuda_runtime.h>
#include <math.h>

#define HW (768 * 768)
#define HW4 (HW / 4)
#define SPTS 8192
#define NCHUNK 16
#define CHUNK 512                // dst points per chamfer block
#define SRCB 512                 // src points per chamfer block (256 thr x 2)
#define NCH (2 * (SPTS / SRCB) * NCHUNK)   // 512 blocks
#define NMAIN 592
#define NP2 592

// 0 mask,1 nsq,2 den,3 num,4 bce,5 eik,6 sdf,7 con,8 vis,9 derr,10 pc_xy,11 pc_yx
__device__ double g_acc[12];
__device__ unsigned int g_min[2 * SPTS];   // per-source-point min dist^2 (uint-ordered floats >= 0)

typedef unsigned long long u64;

__device__ __forceinline__ u64 fma2(u64 a, u64 b, u64 c) {
    u64 d; asm("fma.rn.f32x2 %0,%1,%2,%3;" : "=l"(d) : "l"(a), "l"(b), "l"(c)); return d;
}
__device__ __forceinline__ u64 pk2(float lo, float hi) {
    u64 d; asm("mov.b64 %0,{%1,%2};" : "=l"(d) : "f"(lo), "f"(hi)); return d;
}
__device__ __forceinline__ void upk(u64 v, float& lo, float& hi) {
    asm("mov.b64 {%0,%1},%2;" : "=f"(lo), "=f"(hi) : "l"(v));
}
__device__ __forceinline__ float warpSum(float v) {
    #pragma unroll
    for (int o = 16; o; o >>= 1) v += __shfl_xor_sync(0xffffffffu, v, o);
    return v;
}

// ---------------------------------------------------------------------------
// Init: zero accumulators, set g_min to +inf
// ---------------------------------------------------------------------------
__global__ void kInit() {
    const int t = blockIdx.x * 256 + threadIdx.x;
    if (t < 12) g_acc[t] = 0.0;
    if (t < 2 * SPTS) g_min[t] = 0x7F800000u;   // +inf
}

// ---------------------------------------------------------------------------
// Chamfer: 512 blocks. Each: 512 src (2/thread) x 512 dst chunk.
// score = |y|^2 - 2 x.y ; atomicMin of (|x|^2 + min score) into g_min.
// ---------------------------------------------------------------------------
__global__ void __launch_bounds__(256) kCham(const float* __restrict__ X,
                                             const float* __restrict__ Y)
{
    __shared__ __align__(16) float sh0[CHUNK];
    __shared__ __align__(16) float sh1[CHUNK];
    __shared__ __align__(16) float sh2[CHUNK];
    __shared__ __align__(16) float shw[CHUNK];

    const int b = blockIdx.x;
    const int dir = b >> 8;              // 256 blocks per direction
    const int rem = b & 255;
    const int srcblk = rem >> 4;         // 16 src-blocks of 512
    const int chunk = rem & 15;          // 16 dst-chunks of 512
    const float* __restrict__ src = dir ? Y : X;
    const float* __restrict__ dst = dir ? X : Y;

    const int base = chunk * CHUNK;
    for (int i = threadIdx.x; i < CHUNK; i += 256) {
        float y0 = dst[3 * (base + i) + 0];
        float y1 = dst[3 * (base + i) + 1];
        float y2 = dst[3 * (base + i) + 2];
        sh0[i] = y0; sh1[i] = y1; sh2[i] = y2;
        shw[i] = fmaf(y0, y0, fmaf(y1, y1, y2 * y2));
    }
    __syncthreads();

    u64 A0[2], A1[2], A2[2];
    float XX[2], M0[2], M1[2];
    #pragma unroll
    for (int r = 0; r < 2; r++) {
        int s = srcblk * SRCB + r * 256 + threadIdx.x;
        float x0 = src[3 * s], x1 = src[3 * s + 1], x2 = src[3 * s + 2];
        A0[r] = pk2(-2.0f * x0, -2.0f * x0);
        A1[r] = pk2(-2.0f * x1, -2.0f * x1);
        A2[r] = pk2(-2.0f * x2, -2.0f * x2);
        XX[r] = fmaf(x0, x0, fmaf(x1, x1, x2 * x2));
        M0[r] = 3.0e38f; M1[r] = 3.0e38f;
    }

    const u64* __restrict__ q0 = (const u64*)sh0;
    const u64* __restrict__ q1 = (const u64*)sh1;
    const u64* __restrict__ q2 = (const u64*)sh2;
    const u64* __restrict__ qw = (const u64*)shw;

    #pragma unroll 4
    for (int i = 0; i < CHUNK / 4; i++) {
        u64 b0a = q0[2 * i], b0b = q0[2 * i + 1];
        u64 b1a = q1[2 * i], b1b = q1[2 * i + 1];
        u64 b2a = q2[2 * i], b2b = q2[2 * i + 1];
        u64 wa  = qw[2 * i], wb  = qw[2 * i + 1];
        #pragma unroll
        for (int r = 0; r < 2; r++) {
            u64 sA = fma2(A0[r], b0a, fma2(A1[r], b1a, fma2(A2[r], b2a, wa)));
            u64 sB = fma2(A0[r], b0b, fma2(A1[r], b1b, fma2(A2[r], b2b, wb)));
            float lo, hi;
            upk(sA, lo, hi); M0[r] = fminf(M0[r], lo); M1[r] = fminf(M1[r], hi);
            upk(sB, lo, hi); M0[r] = fminf(M0[r], lo); M1[r] = fminf(M1[r], hi);
        }
    }
    #pragma unroll
    for (int r = 0; r < 2; r++) {
        int s = srcblk * SRCB + r * 256 + threadIdx.x;
        float v = fmaxf(XX[r] + fminf(M0[r], M1[r]), 0.0f);   // >=0: uint order == float order
        atomicMin(&g_min[(dir << 13) + s], __float_as_uint(v));
    }
}

// ---------------------------------------------------------------------------
// Main streaming reductions -> global double atomics (hardware RED.ADD.F64)
// ---------------------------------------------------------------------------
__global__ void __launch_bounds__(256) kMain(
    const float* __restrict__ npred, const float* __restrict__ ngt,
    const float* __restrict__ dpred, const float* __restrict__ dgt,
    const float* __restrict__ mask,  const float* __restrict__ comp,
    const float* __restrict__ grad,  const float* __restrict__ sdf,
    const float* __restrict__ nwa,   const float* __restrict__ vis,
    const float* __restrict__ w, int N, int P, int C)
{
    const int tid = blockIdx.x * 256 + threadIdx.x;
    const int stride = NMAIN * 256;

    float s_mask = 0.f, s_nsq = 0.f, s_den = 0.f, s_num = 0.f, s_bce = 0.f;
    const float4* __restrict__ mk4 = (const float4*)mask;
    const float4* __restrict__ cp4 = (const float4*)comp;
    const float4* __restrict__ dg4 = (const float4*)dgt;
    const float4* __restrict__ dp4 = (const float4*)dpred;
    const float4* __restrict__ np4 = (const float4*)npred;
    const float4* __restrict__ ng4 = (const float4*)ngt;

    for (int g = tid; g < HW4; g += stride) {
        float4 mk = mk4[g];
        float m0 = mk.x > 0.5f ? 1.f : 0.f;
        float m1 = mk.y > 0.5f ? 1.f : 0.f;
        float m2 = mk.z > 0.5f ? 1.f : 0.f;
        float m3 = mk.w > 0.5f ? 1.f : 0.f;
        s_mask += (m0 + m1) + (m2 + m3);

        float4 A0 = np4[3 * g], A1 = np4[3 * g + 1], A2 = np4[3 * g + 2];
        float4 B0 = ng4[3 * g], B1 = ng4[3 * g + 1], B2 = ng4[3 * g + 2];
        float d0x = A0.x - B0.x, d0y = A0.y - B0.y, d0z = A0.z - B0.z;
        float d1x = A0.w - B0.w, d1y = A1.x - B1.x, d1z = A1.y - B1.y;
        float d2x = A1.z - B1.z, d2y = A1.w - B1.w, d2z = A2.x - B2.x;
        float d3x = A2.y - B2.y, d3y = A2.z - B2.z, d3z = A2.w - B2.w;
        s_nsq += m0 * fmaf(d0x, d0x, fmaf(d0y, d0y, d0z * d0z));
        s_nsq += m1 * fmaf(d1x, d1x, fmaf(d1y, d1y, d1z * d1z));
        s_nsq += m2 * fmaf(d2x, d2x, fmaf(d2y, d2y, d2z * d2z));
        s_nsq += m3 * fmaf(d3x, d3x, fmaf(d3y, d3y, d3z * d3z));

        float4 dg = dg4[g], dp = dp4[g];
        float vg0 = dg.x * m0, vg1 = dg.y * m1, vg2 = dg.z * m2, vg3 = dg.w * m3;
        float vp0 = dp.x * m0, vp1 = dp.y * m1, vp2 = dp.z * m2, vp3 = dp.w * m3;
        s_den = fmaf(vg0, vg0, fmaf(vg1, vg1, fmaf(vg2, vg2, fmaf(vg3, vg3, s_den))));
        s_num = fmaf(vg0, vp0, fmaf(vg1, vp1, fmaf(vg2, vp2, fmaf(vg3, vp3, s_num))));

        float4 c = cp4[g];
        float c0 = fminf(fmaxf(c.x, 1e-5f), 1.0f - 1e-5f);
        float c1 = fminf(fmaxf(c.y, 1e-5f), 1.0f - 1e-5f);
        float c2 = fminf(fmaxf(c.z, 1e-5f), 1.0f - 1e-5f);
        float c3 = fminf(fmaxf(c.w, 1e-5f), 1.0f - 1e-5f);
        s_bce -= m0 * __logf(c0) + (1.0f - m0) * __logf(1.0f - c0);
        s_bce -= m1 * __logf(c1) + (1.0f - m1) * __logf(1.0f - c1);
        s_bce -= m2 * __logf(c2) + (1.0f - m2) * __logf(1.0f - c2);
        s_bce -= m3 * __logf(c3) + (1.0f - m3) * __logf(1.0f - c3);
    }

    float s_eik = 0.f, s_sdf = 0.f;
    const float4* __restrict__ gr4 = (const float4*)grad;
    const float4* __restrict__ sd4 = (const float4*)sdf;
    const int N4 = N / 4;
    for (int g = tid; g < N4; g += stride) {
        float4 G0 = gr4[3 * g], G1 = gr4[3 * g + 1], G2 = gr4[3 * g + 2];
        float n0 = sqrtf(fmaf(G0.x, G0.x, fmaf(G0.y, G0.y, G0.z * G0.z))) - 1.0f;
        float n1 = sqrtf(fmaf(G0.w, G0.w, fmaf(G1.x, G1.x, G1.y * G1.y))) - 1.0f;
        float n2 = sqrtf(fmaf(G1.z, G1.z, fmaf(G1.w, G1.w, G2.x * G2.x))) - 1.0f;
        float n3 = sqrtf(fmaf(G2.y, G2.y, fmaf(G2.z, G2.z, G2.w * G2.w))) - 1.0f;
        s_eik += fmaf(n0, n0, fmaf(n1, n1, fmaf(n2, n2, n3 * n3)));
        float4 s = sd4[g];
        s_sdf += fabsf(s.x) + fabsf(s.y) + fabsf(s.z) + fabsf(s.w);
    }
    for (int i = N4 * 4 + tid; i < N; i += stride) {
        float g0 = grad[3 * i], g1 = grad[3 * i + 1], g2 = grad[3 * i + 2];
        float d = sqrtf(fmaf(g0, g0, fmaf(g1, g1, g2 * g2))) - 1.0f;
        s_eik = fmaf(d, d, s_eik);
        s_sdf += fabsf(sdf[i]);
    }

    float s_con = 0.f, s_vis = 0.f;
    if (C == 4) {
        const float4* __restrict__ nw4 = (const float4*)nwa;
        const float4* __restrict__ vi4 = (const float4*)vis;
        for (int p = tid; p < P; p += stride) {
            float4 P0 = nw4[3 * p], P1 = nw4[3 * p + 1], P2 = nw4[3 * p + 2];
            float4 V = vi4[p];
            float wp = w[p];
            float dx, dy, dz, mse, vv;
            dx = P0.x - P0.w; dy = P0.y - P1.x; dz = P0.z - P1.y;
            mse = fmaf(dx, dx, fmaf(dy, dy, dz * dz)); vv = V.x * V.y;
            s_vis += vv; s_con = fmaf(mse * vv, wp, s_con);
            dx = P0.w - P1.z; dy = P1.x - P1.w; dz = P1.y - P2.x;
            mse = fmaf(dx, dx, fmaf(dy, dy, dz * dz)); vv = V.y * V.z;
            s_vis += vv; s_con = fmaf(mse * vv, wp, s_con);
            dx = P1.z - P2.y; dy = P1.w - P2.z; dz = P2.x - P2.w;
            mse = fmaf(dx, dx, fmaf(dy, dy, dz * dz)); vv = V.z * V.w;
            s_vis += vv; s_con = fmaf(mse * vv, wp, s_con);
        }
    } else {
        for (int p = tid; p < P; p += stride) {
            float wp = w[p];
            const float* np_ = nwa + (size_t)p * C * 3;
            const float* vp_ = vis + (size_t)p * C;
            float px = np_[0], py = np_[1], pz = np_[2], pv = vp_[0];
            for (int i = 1; i < C; i++) {
                float cx = np_[3 * i], cy = np_[3 * i + 1], cz = np_[3 * i + 2];
                float cv = vp_[i];
                float dx = px - cx, dy = py - cy, dz = pz - cz;
                float mse = fmaf(dx, dx, fmaf(dy, dy, dz * dz));
                float vv = pv * cv;
                s_vis += vv;
                s_con = fmaf(mse * vv, wp, s_con);
                px = cx; py = cy; pz = cz; pv = cv;
            }
        }
    }

    __shared__ float shred[9];
    if (threadIdx.x < 9) shred[threadIdx.x] = 0.f;
    __syncthreads();
    float vals[9] = {s_mask, s_nsq, s_den, s_num, s_bce, s_eik, s_sdf, s_con, s_vis};
    #pragma unroll
    for (int k = 0; k < 9; k++) {
        float r = warpSum(vals[k]);
        if ((threadIdx.x & 31) == 0) atomicAdd(&shred[k], r);
    }
    __syncthreads();
    if (threadIdx.x < 9) atomicAdd(&g_acc[threadIdx.x], (double)shred[threadIdx.x]);
}

// ---------------------------------------------------------------------------
// Pass 2: depth |vg*scale - vp| + chamfer sqrt-sum over g_min (64KB)
// ---------------------------------------------------------------------------
__global__ void __launch_bounds__(256) kP2(
    const float* __restrict__ dpred, const float* __restrict__ dgt,
    const float* __restrict__ mask)
{
    const float den = (float)g_acc[2];
    const float num = (float)g_acc[3];
    float scale = num / den;
    if (!isfinite(scale)) scale = 1.0f;

    const int tid = blockIdx.x * 256 + threadIdx.x;
    const int stride = NP2 * 256;

    const float4* __restrict__ mk4 = (const float4*)mask;
    const float4* __restrict__ dg4 = (const float4*)dgt;
    const float4* __restrict__ dp4 = (const float4*)dpred;

    float s_derr = 0.f;
    for (int g = tid; g < HW4; g += stride) {
        float4 mk = mk4[g];
        float4 dg = dg4[g], dp = dp4[g];
        float m0 = mk.x > 0.5f ? 1.f : 0.f;
        float m1 = mk.y > 0.5f ? 1.f : 0.f;
        float m2 = mk.z > 0.5f ? 1.f : 0.f;
        float m3 = mk.w > 0.5f ? 1.f : 0.f;
        s_derr += fabsf(fmaf(dg.x * m0, scale, -dp.x * m0));
        s_derr += fabsf(fmaf(dg.y * m1, scale, -dp.y * m1));
        s_derr += fabsf(fmaf(dg.z * m2, scale, -dp.z * m2));
        s_derr += fabsf(fmaf(dg.w * m3, scale, -dp.w * m3));
    }

    float s0 = 0.f, s1 = 0.f;
    for (int s = tid; s < 2 * SPTS; s += stride) {
        float d = sqrtf(__uint_as_float(g_min[s]));
        if (s < SPTS) s0 += d; else s1 += d;
    }

    __shared__ float shred[3];
    if (threadIdx.x < 3) shred[threadIdx.x] = 0.f;
    __syncthreads();
    float vals[3] = {s_derr, s0, s1};
    #pragma unroll
    for (int k = 0; k < 3; k++) {
        float r = warpSum(vals[k]);
        if ((threadIdx.x & 31) == 0) atomicAdd(&shred[k], r);
    }
    __syncthreads();
    if (threadIdx.x < 3) atomicAdd(&g_acc[9 + threadIdx.x], (double)shred[threadIdx.x]);
}

// ---------------------------------------------------------------------------
// Final combine: single thread, FP32 math (no software DDIV chains)
// ---------------------------------------------------------------------------
__global__ void kFin(float* __restrict__ out, int out_size, int N)
{
    // independent loads first (batched by compiler), then cheap fp32 divides
    float a0 = (float)g_acc[0], a1 = (float)g_acc[1], a2 = (float)g_acc[2];
    float a4 = (float)g_acc[4], a5 = (float)g_acc[5], a6 = (float)g_acc[6];
    float a7 = (float)g_acc[7], a8 = (float)g_acc[8], a9 = (float)g_acc[9];
    float a10 = (float)g_acc[10], a11 = (float)g_acc[11];

    float mask_sum = a0 + 1e-5f;
    float normal_loss = a1 / mask_sum;
    float depth_loss = a9 / (mask_sum + 1e-8f);
    if (a2 < 1e-10f || !isfinite(depth_loss)) depth_loss = 0.0f;
    float pc = (a10 + a11) * (1.0f / (float)SPTS);
    float bce = a4 * (1.0f / (float)HW);
    float inv_n = 1.0f / (float)N;
    float eik = a5 * inv_n;
    float sdfl = a6 * inv_n;
    float con = (a8 > 0.0f) ? a7 / a8 : 0.0f;
    float loss = normal_loss + depth_loss + pc + bce + eik + sdfl + con;
    for (int i = 0; i < out_size; i++) out[i] = loss;
}

extern "C" void kernel_launch(void* const* d_in, const int* in_sizes, int n_in,
                              void* d_out, int out_size)
{
    const float* npred = (const float*)d_in[0];
    const float* ngt   = (const float*)d_in[1];
    const float* dpred = (const float*)d_in[2];
    const float* dgt   = (const float*)d_in[3];
    const float* X     = (const float*)d_in[4];
    const float* Y     = (const float*)d_in[5];
    const float* mask  = (const float*)d_in[6];
    const float* comp  = (const float*)d_in[7];
    const float* grad  = (const float*)d_in[8];
    const float* sdf   = (const float*)d_in[9];
    const float* nwa   = (const float*)d_in[10];
    const float* vis   = (const float*)d_in[11];
    const float* w     = (const float*)d_in[12];

    int N = in_sizes[9];
    int P = in_sizes[12];
    int C = in_sizes[11] / P;

    kInit<<<64, 256>>>();
    kCham<<<NCH, 256>>>(X, Y);
    kMain<<<NMAIN, 256>>>(npred, ngt, dpred, dgt, mask, comp, grad, sdf, nwa, vis, w, N, P, C);
    kP2<<<NP2, 256>>>(dpred, dgt, mask);
    kFin<<<1, 1>>>((float*)d_out, out_size, N);
}

// round 13
// speedup vs baseline: 1.7065x; 1.0638x over previous
#include <cuda_runtime.h>
#include <math.h>

#define HW (768 * 768)
#define HW4 (HW / 4)
#define SPTS 8192
#define CHUNK 256                 // dst points per chamfer block
#define SRCB 1024                 // src points per chamfer block (256 thr x 4)
#define NCH 512                   // 2 dir * 8 srcblk * 32 chunk
#define NMAIN 592
#define NP2 592

// 0 mask,1 nsq,2 den,3 num,4 bce,5 eik,6 sdf,7 con,8 vis,9 derr,10 pc_xy,11 pc_yx
__device__ double g_acc[12];                  // zero-init = valid initial state
__device__ unsigned int g_min[2 * SPTS];      // stores ~float_bits(min d2); 0 == identity for atomicMax
__device__ unsigned int g_done;               // kP2 completion counter (zero-init; reset each replay)

typedef unsigned long long u64;

__device__ __forceinline__ u64 fma2(u64 a, u64 b, u64 c) {
    u64 d; asm("fma.rn.f32x2 %0,%1,%2,%3;" : "=l"(d) : "l"(a), "l"(b), "l"(c)); return d;
}
__device__ __forceinline__ u64 pk2(float lo, float hi) {
    u64 d; asm("mov.b64 %0,{%1,%2};" : "=l"(d) : "f"(lo), "f"(hi)); return d;
}
__device__ __forceinline__ void upk(u64 v, float& lo, float& hi) {
    asm("mov.b64 {%0,%1},%2;" : "=f"(lo), "=f"(hi) : "l"(v));
}
__device__ __forceinline__ float warpSum(float v) {
    #pragma unroll
    for (int o = 16; o; o >>= 1) v += __shfl_xor_sync(0xffffffffu, v, o);
    return v;
}

// ---------------------------------------------------------------------------
// Chamfer: 512 blocks. Each: 1024 src (4/thread) x 256 dst chunk.
// score = |y|^2 - 2 x.y ; atomicMax(~bits(|x|^2 + min score)) so zero-init works.
// ---------------------------------------------------------------------------
__global__ void __launch_bounds__(256) kCham(const float* __restrict__ X,
                                             const float* __restrict__ Y)
{
    __shared__ __align__(16) float sh0[CHUNK];
    __shared__ __align__(16) float sh1[CHUNK];
    __shared__ __align__(16) float sh2[CHUNK];
    __shared__ __align__(16) float shw[CHUNK];

    const int b = blockIdx.x;
    const int dir = b >> 8;              // 256 blocks per direction
    const int rem = b & 255;
    const int srcblk = rem >> 5;         // 8 src-blocks of 1024
    const int chunk = rem & 31;          // 32 dst-chunks of 256
    const float* __restrict__ src = dir ? Y : X;
    const float* __restrict__ dst = dir ? X : Y;

    const int base = chunk * CHUNK;
    if (threadIdx.x < CHUNK) {
        int i = threadIdx.x;
        float y0 = dst[3 * (base + i) + 0];
        float y1 = dst[3 * (base + i) + 1];
        float y2 = dst[3 * (base + i) + 2];
        sh0[i] = y0; sh1[i] = y1; sh2[i] = y2;
        shw[i] = fmaf(y0, y0, fmaf(y1, y1, y2 * y2));
    }
    __syncthreads();

    u64 A0[4], A1[4], A2[4];
    float XX[4], M0[4], M1[4];
    #pragma unroll
    for (int r = 0; r < 4; r++) {
        int s = srcblk * SRCB + r * 256 + threadIdx.x;
        float x0 = src[3 * s], x1 = src[3 * s + 1], x2 = src[3 * s + 2];
        A0[r] = pk2(-2.0f * x0, -2.0f * x0);
        A1[r] = pk2(-2.0f * x1, -2.0f * x1);
        A2[r] = pk2(-2.0f * x2, -2.0f * x2);
        XX[r] = fmaf(x0, x0, fmaf(x1, x1, x2 * x2));
        M0[r] = 3.0e38f; M1[r] = 3.0e38f;
    }

    const u64* __restrict__ q0 = (const u64*)sh0;
    const u64* __restrict__ q1 = (const u64*)sh1;
    const u64* __restrict__ q2 = (const u64*)sh2;
    const u64* __restrict__ qw = (const u64*)shw;

    #pragma unroll 2
    for (int i = 0; i < CHUNK / 4; i++) {
        u64 b0a = q0[2 * i], b0b = q0[2 * i + 1];
        u64 b1a = q1[2 * i], b1b = q1[2 * i + 1];
        u64 b2a = q2[2 * i], b2b = q2[2 * i + 1];
        u64 wa  = qw[2 * i], wb  = qw[2 * i + 1];
        #pragma unroll
        for (int r = 0; r < 4; r++) {
            u64 sA = fma2(A0[r], b0a, fma2(A1[r], b1a, fma2(A2[r], b2a, wa)));
            u64 sB = fma2(A0[r], b0b, fma2(A1[r], b1b, fma2(A2[r], b2b, wb)));
            float lo, hi;
            upk(sA, lo, hi); M0[r] = fminf(M0[r], lo); M1[r] = fminf(M1[r], hi);
            upk(sB, lo, hi); M0[r] = fminf(M0[r], lo); M1[r] = fminf(M1[r], hi);
        }
    }
    #pragma unroll
    for (int r = 0; r < 4; r++) {
        int s = srcblk * SRCB + r * 256 + threadIdx.x;
        float v = fmaxf(XX[r] + fminf(M0[r], M1[r]), 0.0f);   // >=0
        atomicMax(&g_min[(dir << 13) + s], ~__float_as_uint(v));
    }
}

// ---------------------------------------------------------------------------
// Main streaming reductions -> global double atomics (hardware RED.ADD.F64)
// ---------------------------------------------------------------------------
__global__ void __launch_bounds__(256) kMain(
    const float* __restrict__ npred, const float* __restrict__ ngt,
    const float* __restrict__ dpred, const float* __restrict__ dgt,
    const float* __restrict__ mask,  const float* __restrict__ comp,
    const float* __restrict__ grad,  const float* __restrict__ sdf,
    const float* __restrict__ nwa,   const float* __restrict__ vis,
    const float* __restrict__ w, int N, int P, int C)
{
    const int tid = blockIdx.x * 256 + threadIdx.x;
    const int stride = NMAIN * 256;

    float s_mask = 0.f, s_nsq = 0.f, s_den = 0.f, s_num = 0.f, s_bce = 0.f;
    const float4* __restrict__ mk4 = (const float4*)mask;
    const float4* __restrict__ cp4 = (const float4*)comp;
    const float4* __restrict__ dg4 = (const float4*)dgt;
    const float4* __restrict__ dp4 = (const float4*)dpred;
    const float4* __restrict__ np4 = (const float4*)npred;
    const float4* __restrict__ ng4 = (const float4*)ngt;

    for (int g = tid; g < HW4; g += stride) {
        float4 mk = mk4[g];
        float m0 = mk.x > 0.5f ? 1.f : 0.f;
        float m1 = mk.y > 0.5f ? 1.f : 0.f;
        float m2 = mk.z > 0.5f ? 1.f : 0.f;
        float m3 = mk.w > 0.5f ? 1.f : 0.f;
        s_mask += (m0 + m1) + (m2 + m3);

        float4 A0 = np4[3 * g], A1 = np4[3 * g + 1], A2 = np4[3 * g + 2];
        float4 B0 = ng4[3 * g], B1 = ng4[3 * g + 1], B2 = ng4[3 * g + 2];
        float d0x = A0.x - B0.x, d0y = A0.y - B0.y, d0z = A0.z - B0.z;
        float d1x = A0.w - B0.w, d1y = A1.x - B1.x, d1z = A1.y - B1.y;
        float d2x = A1.z - B1.z, d2y = A1.w - B1.w, d2z = A2.x - B2.x;
        float d3x = A2.y - B2.y, d3y = A2.z - B2.z, d3z = A2.w - B2.w;
        s_nsq += m0 * fmaf(d0x, d0x, fmaf(d0y, d0y, d0z * d0z));
        s_nsq += m1 * fmaf(d1x, d1x, fmaf(d1y, d1y, d1z * d1z));
        s_nsq += m2 * fmaf(d2x, d2x, fmaf(d2y, d2y, d2z * d2z));
        s_nsq += m3 * fmaf(d3x, d3x, fmaf(d3y, d3y, d3z * d3z));

        float4 dg = dg4[g], dp = dp4[g];
        float vg0 = dg.x * m0, vg1 = dg.y * m1, vg2 = dg.z * m2, vg3 = dg.w * m3;
        float vp0 = dp.x * m0, vp1 = dp.y * m1, vp2 = dp.z * m2, vp3 = dp.w * m3;
        s_den = fmaf(vg0, vg0, fmaf(vg1, vg1, fmaf(vg2, vg2, fmaf(vg3, vg3, s_den))));
        s_num = fmaf(vg0, vp0, fmaf(vg1, vp1, fmaf(vg2, vp2, fmaf(vg3, vp3, s_num))));

        float4 c = cp4[g];
        float c0 = fminf(fmaxf(c.x, 1e-5f), 1.0f - 1e-5f);
        float c1 = fminf(fmaxf(c.y, 1e-5f), 1.0f - 1e-5f);
        float c2 = fminf(fmaxf(c.z, 1e-5f), 1.0f - 1e-5f);
        float c3 = fminf(fmaxf(c.w, 1e-5f), 1.0f - 1e-5f);
        s_bce -= m0 * __logf(c0) + (1.0f - m0) * __logf(1.0f - c0);
        s_bce -= m1 * __logf(c1) + (1.0f - m1) * __logf(1.0f - c1);
        s_bce -= m2 * __logf(c2) + (1.0f - m2) * __logf(1.0f - c2);
        s_bce -= m3 * __logf(c3) + (1.0f - m3) * __logf(1.0f - c3);
    }

    float s_eik = 0.f, s_sdf = 0.f;
    const float4* __restrict__ gr4 = (const float4*)grad;
    const float4* __restrict__ sd4 = (const float4*)sdf;
    const int N4 = N / 4;
    for (int g = tid; g < N4; g += stride) {
        float4 G0 = gr4[3 * g], G1 = gr4[3 * g + 1], G2 = gr4[3 * g + 2];
        float n0 = sqrtf(fmaf(G0.x, G0.x, fmaf(G0.y, G0.y, G0.z * G0.z))) - 1.0f;
        float n1 = sqrtf(fmaf(G0.w, G0.w, fmaf(G1.x, G1.x, G1.y * G1.y))) - 1.0f;
        float n2 = sqrtf(fmaf(G1.z, G1.z, fmaf(G1.w, G1.w, G2.x * G2.x))) - 1.0f;
        float n3 = sqrtf(fmaf(G2.y, G2.y, fmaf(G2.z, G2.z, G2.w * G2.w))) - 1.0f;
        s_eik += fmaf(n0, n0, fmaf(n1, n1, fmaf(n2, n2, n3 * n3)));
        float4 s = sd4[g];
        s_sdf += fabsf(s.x) + fabsf(s.y) + fabsf(s.z) + fabsf(s.w);
    }
    for (int i = N4 * 4 + tid; i < N; i += stride) {
        float g0 = grad[3 * i], g1 = grad[3 * i + 1], g2 = grad[3 * i + 2];
        float d = sqrtf(fmaf(g0, g0, fmaf(g1, g1, g2 * g2))) - 1.0f;
        s_eik = fmaf(d, d, s_eik);
        s_sdf += fabsf(sdf[i]);
    }

    float s_con = 0.f, s_vis = 0.f;
    if (C == 4) {
        const float4* __restrict__ nw4 = (const float4*)nwa;
        const float4* __restrict__ vi4 = (const float4*)vis;
        for (int p = tid; p < P; p += stride) {
            float4 P0 = nw4[3 * p], P1 = nw4[3 * p + 1], P2 = nw4[3 * p + 2];
            float4 V = vi4[p];
            float wp = w[p];
            float dx, dy, dz, mse, vv;
            dx = P0.x - P0.w; dy = P0.y - P1.x; dz = P0.z - P1.y;
            mse = fmaf(dx, dx, fmaf(dy, dy, dz * dz)); vv = V.x * V.y;
            s_vis += vv; s_con = fmaf(mse * vv, wp, s_con);
            dx = P0.w - P1.z; dy = P1.x - P1.w; dz = P1.y - P2.x;
            mse = fmaf(dx, dx, fmaf(dy, dy, dz * dz)); vv = V.y * V.z;
            s_vis += vv; s_con = fmaf(mse * vv, wp, s_con);
            dx = P1.z - P2.y; dy = P1.w - P2.z; dz = P2.x - P2.w;
            mse = fmaf(dx, dx, fmaf(dy, dy, dz * dz)); vv = V.z * V.w;
            s_vis += vv; s_con = fmaf(mse * vv, wp, s_con);
        }
    } else {
        for (int p = tid; p < P; p += stride) {
            float wp = w[p];
            const float* np_ = nwa + (size_t)p * C * 3;
            const float* vp_ = vis + (size_t)p * C;
            float px = np_[0], py = np_[1], pz = np_[2], pv = vp_[0];
            for (int i = 1; i < C; i++) {
                float cx = np_[3 * i], cy = np_[3 * i + 1], cz = np_[3 * i + 2];
                float cv = vp_[i];
                float dx = px - cx, dy = py - cy, dz = pz - cz;
                float mse = fmaf(dx, dx, fmaf(dy, dy, dz * dz));
                float vv = pv * cv;
                s_vis += vv;
                s_con = fmaf(mse * vv, wp, s_con);
                px = cx; py = cy; pz = cz; pv = cv;
            }
        }
    }

    __shared__ float shred[9];
    if (threadIdx.x < 9) shred[threadIdx.x] = 0.f;
    __syncthreads();
    float vals[9] = {s_mask, s_nsq, s_den, s_num, s_bce, s_eik, s_sdf, s_con, s_vis};
    #pragma unroll
    for (int k = 0; k < 9; k++) {
        float r = warpSum(vals[k]);
        if ((threadIdx.x & 31) == 0) atomicAdd(&shred[k], r);
    }
    __syncthreads();
    if (threadIdx.x < 9) atomicAdd(&g_acc[threadIdx.x], (double)shred[threadIdx.x]);
}

// ---------------------------------------------------------------------------
// Pass 2: depth |vg*scale - vp| + chamfer sqrt-sum + last-block finalize.
// Also resets g_min / g_acc / g_done for the next graph replay.
// ---------------------------------------------------------------------------
__global__ void __launch_bounds__(256) kP2(
    const float* __restrict__ dpred, const float* __restrict__ dgt,
    const float* __restrict__ mask, float* __restrict__ out, int out_size, int N)
{
    const float den = (float)g_acc[2];
    const float num = (float)g_acc[3];
    float scale = num / den;
    if (!isfinite(scale)) scale = 1.0f;

    const int tid = blockIdx.x * 256 + threadIdx.x;
    const int stride = NP2 * 256;

    const float4* __restrict__ mk4 = (const float4*)mask;
    const float4* __restrict__ dg4 = (const float4*)dgt;
    const float4* __restrict__ dp4 = (const float4*)dpred;

    float s_derr = 0.f;
    for (int g = tid; g < HW4; g += stride) {
        float4 mk = mk4[g];
        float4 dg = dg4[g], dp = dp4[g];
        float m0 = mk.x > 0.5f ? 1.f : 0.f;
        float m1 = mk.y > 0.5f ? 1.f : 0.f;
        float m2 = mk.z > 0.5f ? 1.f : 0.f;
        float m3 = mk.w > 0.5f ? 1.f : 0.f;
        s_derr += fabsf(fmaf(dg.x * m0, scale, -dp.x * m0));
        s_derr += fabsf(fmaf(dg.y * m1, scale, -dp.y * m1));
        s_derr += fabsf(fmaf(dg.z * m2, scale, -dp.z * m2));
        s_derr += fabsf(fmaf(dg.w * m3, scale, -dp.w * m3));
    }

    float s0 = 0.f, s1 = 0.f;
    for (int s = tid; s < 2 * SPTS; s += stride) {
        float d = sqrtf(__uint_as_float(~g_min[s]));
        g_min[s] = 0u;                       // reset for next replay
        if (s < SPTS) s0 += d; else s1 += d;
    }

    __shared__ float shred[3];
    __shared__ unsigned int s_last;
    if (threadIdx.x < 3) shred[threadIdx.x] = 0.f;
    __syncthreads();
    float vals[3] = {s_derr, s0, s1};
    #pragma unroll
    for (int k = 0; k < 3; k++) {
        float r = warpSum(vals[k]);
        if ((threadIdx.x & 31) == 0) atomicAdd(&shred[k], r);
    }
    __syncthreads();
    if (threadIdx.x < 3) atomicAdd(&g_acc[9 + threadIdx.x], (double)shred[threadIdx.x]);

    // --- last-block finalize ---
    __threadfence();
    __syncthreads();
    if (threadIdx.x == 0) s_last = atomicAdd(&g_done, 1u);
    __syncthreads();
    if (s_last == NP2 - 1 && threadIdx.x == 0) {
        __threadfence();
        float a0 = (float)__ldcg(&g_acc[0]), a1 = (float)__ldcg(&g_acc[1]);
        float a2 = (float)__ldcg(&g_acc[2]);
        float a4 = (float)__ldcg(&g_acc[4]), a5 = (float)__ldcg(&g_acc[5]);
        float a6 = (float)__ldcg(&g_acc[6]), a7 = (float)__ldcg(&g_acc[7]);
        float a8 = (float)__ldcg(&g_acc[8]), a9 = (float)__ldcg(&g_acc[9]);
        float a10 = (float)__ldcg(&g_acc[10]), a11 = (float)__ldcg(&g_acc[11]);

        float mask_sum = a0 + 1e-5f;
        float normal_loss = a1 / mask_sum;
        float depth_loss = a9 / (mask_sum + 1e-8f);
        if (a2 < 1e-10f || !isfinite(depth_loss)) depth_loss = 0.0f;
        float pc = (a10 + a11) * (1.0f / (float)SPTS);
        float bce = a4 * (1.0f / (float)HW);
        float inv_n = 1.0f / (float)N;
        float eik = a5 * inv_n;
        float sdfl = a6 * inv_n;
        float con = (a8 > 0.0f) ? a7 / a8 : 0.0f;
        float loss = normal_loss + depth_loss + pc + bce + eik + sdfl + con;
        for (int i = 0; i < out_size; i++) out[i] = loss;

        #pragma unroll
        for (int k = 0; k < 12; k++) g_acc[k] = 0.0;   // reset for next replay
        g_done = 0u;
    }
}

extern "C" void kernel_launch(void* const* d_in, const int* in_sizes, int n_in,
                              void* d_out, int out_size)
{
    const float* npred = (const float*)d_in[0];
    const float* ngt   = (const float*)d_in[1];
    const float* dpred = (const float*)d_in[2];
    const float* dgt   = (const float*)d_in[3];
    const float* X     = (const float*)d_in[4];
    const float* Y     = (const float*)d_in[5];
    const float* mask  = (const float*)d_in[6];
    const float* comp  = (const float*)d_in[7];
    const float* grad  = (const float*)d_in[8];
    const float* sdf   = (const float*)d_in[9];
    const float* nwa   = (const float*)d_in[10];
    const float* vis   = (const float*)d_in[11];
    const float* w     = (const float*)d_in[12];

    int N = in_sizes[9];
    int P = in_sizes[12];
    int C = in_sizes[11] / P;

    // One-time handle creation (host-side only; no device memory).
    static cudaStream_t s2 = nullptr;
    static cudaEvent_t evF = nullptr, evJ = nullptr;
    if (!s2) {
        cudaStreamCreateWithFlags(&s2, cudaStreamNonBlocking);
        cudaEventCreateWithFlags(&evF, cudaEventDisableTiming);
        cudaEventCreateWithFlags(&evJ, cudaEventDisableTiming);
    }

    // Fork: kCham on s2 concurrent with kMain on the main stream; join before kP2.
    cudaEventRecord(evF, 0);
    cudaStreamWaitEvent(s2, evF, 0);
    kCham<<<NCH, 256, 0, s2>>>(X, Y);
    cudaEventRecord(evJ, s2);

    kMain<<<NMAIN, 256>>>(npred, ngt, dpred, dgt, mask, comp, grad, sdf, nwa, vis, w, N, P, C);

    cudaStreamWaitEvent(0, evJ, 0);
    kP2<<<NP2, 256>>>(dpred, dgt, mask, (float*)d_out, out_size, N);
}

// round 14
// speedup vs baseline: 1.8516x; 1.0851x over previous
#include <cuda_runtime.h>
#include <math.h>

#define HW (768 * 768)
#define HW4 (HW / 4)
#define SPTS 8192
#define CHUNK 256                 // dst points per chamfer block
#define CTHR 128                  // chamfer block threads
#define SRCB 512                  // src points per chamfer block (128 thr x 4)
#define NCH 1024                  // 2 dir * 16 srcblk * 32 chunk
#define NMAIN 592
#define NP2 592

// 0 mask,1 nsq,2 den,3 num,4 bce,5 eik,6 sdf,7 con,8 vis,9 derr,10 pc_xy,11 pc_yx
__device__ double g_acc[12];                  // zero-init = valid initial state
__device__ unsigned int g_min[2 * SPTS];      // stores ~float_bits(min d2); 0 == identity for atomicMax
__device__ unsigned int g_done;               // kP2 completion counter (zero-init; reset each replay)

typedef unsigned long long u64;

__device__ __forceinline__ u64 fma2(u64 a, u64 b, u64 c) {
    u64 d; asm("fma.rn.f32x2 %0,%1,%2,%3;" : "=l"(d) : "l"(a), "l"(b), "l"(c)); return d;
}
__device__ __forceinline__ u64 pk2(float lo, float hi) {
    u64 d; asm("mov.b64 %0,{%1,%2};" : "=l"(d) : "f"(lo), "f"(hi)); return d;
}
__device__ __forceinline__ void upk(u64 v, float& lo, float& hi) {
    asm("mov.b64 {%0,%1},%2;" : "=f"(lo), "=f"(hi) : "l"(v));
}
__device__ __forceinline__ float warpSum(float v) {
    #pragma unroll
    for (int o = 16; o; o >>= 1) v += __shfl_xor_sync(0xffffffffu, v, o);
    return v;
}

// ---------------------------------------------------------------------------
// Chamfer: 1024 blocks of 128 threads. Each: 512 src (4/thread) x 256 dst.
// score = |y|^2 - 2 x.y ; atomicMax(~bits(|x|^2 + min score)) so zero-init works.
// 128-thread blocks -> 8 CTA/SM at 64 regs -> 50% occupancy (latency hiding).
// ---------------------------------------------------------------------------
__global__ void __launch_bounds__(CTHR) kCham(const float* __restrict__ X,
                                              const float* __restrict__ Y)
{
    __shared__ __align__(16) float sh0[CHUNK];
    __shared__ __align__(16) float sh1[CHUNK];
    __shared__ __align__(16) float sh2[CHUNK];
    __shared__ __align__(16) float shw[CHUNK];

    const int b = blockIdx.x;
    const int dir = b >> 9;              // 512 blocks per direction
    const int rem = b & 511;
    const int srcblk = rem >> 5;         // 16 src-blocks of 512
    const int chunk = rem & 31;          // 32 dst-chunks of 256
    const float* __restrict__ src = dir ? Y : X;
    const float* __restrict__ dst = dir ? X : Y;

    const int base = chunk * CHUNK;
    for (int i = threadIdx.x; i < CHUNK; i += CTHR) {
        float y0 = dst[3 * (base + i) + 0];
        float y1 = dst[3 * (base + i) + 1];
        float y2 = dst[3 * (base + i) + 2];
        sh0[i] = y0; sh1[i] = y1; sh2[i] = y2;
        shw[i] = fmaf(y0, y0, fmaf(y1, y1, y2 * y2));
    }
    __syncthreads();

    u64 A0[4], A1[4], A2[4];
    float XX[4], M0[4], M1[4];
    #pragma unroll
    for (int r = 0; r < 4; r++) {
        int s = srcblk * SRCB + r * CTHR + threadIdx.x;
        float x0 = src[3 * s], x1 = src[3 * s + 1], x2 = src[3 * s + 2];
        A0[r] = pk2(-2.0f * x0, -2.0f * x0);
        A1[r] = pk2(-2.0f * x1, -2.0f * x1);
        A2[r] = pk2(-2.0f * x2, -2.0f * x2);
        XX[r] = fmaf(x0, x0, fmaf(x1, x1, x2 * x2));
        M0[r] = 3.0e38f; M1[r] = 3.0e38f;
    }

    const u64* __restrict__ q0 = (const u64*)sh0;
    const u64* __restrict__ q1 = (const u64*)sh1;
    const u64* __restrict__ q2 = (const u64*)sh2;
    const u64* __restrict__ qw = (const u64*)shw;

    #pragma unroll 2
    for (int i = 0; i < CHUNK / 4; i++) {
        u64 b0a = q0[2 * i], b0b = q0[2 * i + 1];
        u64 b1a = q1[2 * i], b1b = q1[2 * i + 1];
        u64 b2a = q2[2 * i], b2b = q2[2 * i + 1];
        u64 wa  = qw[2 * i], wb  = qw[2 * i + 1];
        #pragma unroll
        for (int r = 0; r < 4; r++) {
            u64 sA = fma2(A0[r], b0a, fma2(A1[r], b1a, fma2(A2[r], b2a, wa)));
            u64 sB = fma2(A0[r], b0b, fma2(A1[r], b1b, fma2(A2[r], b2b, wb)));
            float lo, hi;
            upk(sA, lo, hi); M0[r] = fminf(M0[r], lo); M1[r] = fminf(M1[r], hi);
            upk(sB, lo, hi); M0[r] = fminf(M0[r], lo); M1[r] = fminf(M1[r], hi);
        }
    }
    #pragma unroll
    for (int r = 0; r < 4; r++) {
        int s = srcblk * SRCB + r * CTHR + threadIdx.x;
        float v = fmaxf(XX[r] + fminf(M0[r], M1[r]), 0.0f);   // >=0
        atomicMax(&g_min[(dir << 13) + s], ~__float_as_uint(v));
    }
}

// ---------------------------------------------------------------------------
// Main streaming reductions -> global double atomics (hardware RED.ADD.F64)
// ---------------------------------------------------------------------------
__global__ void __launch_bounds__(256) kMain(
    const float* __restrict__ npred, const float* __restrict__ ngt,
    const float* __restrict__ dpred, const float* __restrict__ dgt,
    const float* __restrict__ mask,  const float* __restrict__ comp,
    const float* __restrict__ grad,  const float* __restrict__ sdf,
    const float* __restrict__ nwa,   const float* __restrict__ vis,
    const float* __restrict__ w, int N, int P, int C)
{
    const int tid = blockIdx.x * 256 + threadIdx.x;
    const int stride = NMAIN * 256;

    float s_mask = 0.f, s_nsq = 0.f, s_den = 0.f, s_num = 0.f, s_bce = 0.f;
    const float4* __restrict__ mk4 = (const float4*)mask;
    const float4* __restrict__ cp4 = (const float4*)comp;
    const float4* __restrict__ dg4 = (const float4*)dgt;
    const float4* __restrict__ dp4 = (const float4*)dpred;
    const float4* __restrict__ np4 = (const float4*)npred;
    const float4* __restrict__ ng4 = (const float4*)ngt;

    for (int g = tid; g < HW4; g += stride) {
        float4 mk = mk4[g];
        float m0 = mk.x > 0.5f ? 1.f : 0.f;
        float m1 = mk.y > 0.5f ? 1.f : 0.f;
        float m2 = mk.z > 0.5f ? 1.f : 0.f;
        float m3 = mk.w > 0.5f ? 1.f : 0.f;
        s_mask += (m0 + m1) + (m2 + m3);

        float4 A0 = np4[3 * g], A1 = np4[3 * g + 1], A2 = np4[3 * g + 2];
        float4 B0 = ng4[3 * g], B1 = ng4[3 * g + 1], B2 = ng4[3 * g + 2];
        float d0x = A0.x - B0.x, d0y = A0.y - B0.y, d0z = A0.z - B0.z;
        float d1x = A0.w - B0.w, d1y = A1.x - B1.x, d1z = A1.y - B1.y;
        float d2x = A1.z - B1.z, d2y = A1.w - B1.w, d2z = A2.x - B2.x;
        float d3x = A2.y - B2.y, d3y = A2.z - B2.z, d3z = A2.w - B2.w;
        s_nsq += m0 * fmaf(d0x, d0x, fmaf(d0y, d0y, d0z * d0z));
        s_nsq += m1 * fmaf(d1x, d1x, fmaf(d1y, d1y, d1z * d1z));
        s_nsq += m2 * fmaf(d2x, d2x, fmaf(d2y, d2y, d2z * d2z));
        s_nsq += m3 * fmaf(d3x, d3x, fmaf(d3y, d3y, d3z * d3z));

        float4 dg = dg4[g], dp = dp4[g];
        float vg0 = dg.x * m0, vg1 = dg.y * m1, vg2 = dg.z * m2, vg3 = dg.w * m3;
        float vp0 = dp.x * m0, vp1 = dp.y * m1, vp2 = dp.z * m2, vp3 = dp.w * m3;
        s_den = fmaf(vg0, vg0, fmaf(vg1, vg1, fmaf(vg2, vg2, fmaf(vg3, vg3, s_den))));
        s_num = fmaf(vg0, vp0, fmaf(vg1, vp1, fmaf(vg2, vp2, fmaf(vg3, vp3, s_num))));

        float4 c = cp4[g];
        float c0 = fminf(fmaxf(c.x, 1e-5f), 1.0f - 1e-5f);
        float c1 = fminf(fmaxf(c.y, 1e-5f), 1.0f - 1e-5f);
        float c2 = fminf(fmaxf(c.z, 1e-5f), 1.0f - 1e-5f);
        float c3 = fminf(fmaxf(c.w, 1e-5f), 1.0f - 1e-5f);
        s_bce -= m0 * __logf(c0) + (1.0f - m0) * __logf(1.0f - c0);
        s_bce -= m1 * __logf(c1) + (1.0f - m1) * __logf(1.0f - c1);
        s_bce -= m2 * __logf(c2) + (1.0f - m2) * __logf(1.0f - c2);
        s_bce -= m3 * __logf(c3) + (1.0f - m3) * __logf(1.0f - c3);
    }

    float s_eik = 0.f, s_sdf = 0.f;
    const float4* __restrict__ gr4 = (const float4*)grad;
    const float4* __restrict__ sd4 = (const float4*)sdf;
    const int N4 = N / 4;
    for (int g = tid; g < N4; g += stride) {
        float4 G0 = gr4[3 * g], G1 = gr4[3 * g + 1], G2 = gr4[3 * g + 2];
        float n0 = sqrtf(fmaf(G0.x, G0.x, fmaf(G0.y, G0.y, G0.z * G0.z))) - 1.0f;
        float n1 = sqrtf(fmaf(G0.w, G0.w, fmaf(G1.x, G1.x, G1.y * G1.y))) - 1.0f;
        float n2 = sqrtf(fmaf(G1.z, G1.z, fmaf(G1.w, G1.w, G2.x * G2.x))) - 1.0f;
        float n3 = sqrtf(fmaf(G2.y, G2.y, fmaf(G2.z, G2.z, G2.w * G2.w))) - 1.0f;
        s_eik += fmaf(n0, n0, fmaf(n1, n1, fmaf(n2, n2, n3 * n3)));
        float4 s = sd4[g];
        s_sdf += fabsf(s.x) + fabsf(s.y) + fabsf(s.z) + fabsf(s.w);
    }
    for (int i = N4 * 4 + tid; i < N; i += stride) {
        float g0 = grad[3 * i], g1 = grad[3 * i + 1], g2 = grad[3 * i + 2];
        float d = sqrtf(fmaf(g0, g0, fmaf(g1, g1, g2 * g2))) - 1.0f;
        s_eik = fmaf(d, d, s_eik);
        s_sdf += fabsf(sdf[i]);
    }

    float s_con = 0.f, s_vis = 0.f;
    if (C == 4) {
        const float4* __restrict__ nw4 = (const float4*)nwa;
        const float4* __restrict__ vi4 = (const float4*)vis;
        for (int p = tid; p < P; p += stride) {
            float4 P0 = nw4[3 * p], P1 = nw4[3 * p + 1], P2 = nw4[3 * p + 2];
            float4 V = vi4[p];
            float wp = w[p];
            float dx, dy, dz, mse, vv;
            dx = P0.x - P0.w; dy = P0.y - P1.x; dz = P0.z - P1.y;
            mse = fmaf(dx, dx, fmaf(dy, dy, dz * dz)); vv = V.x * V.y;
            s_vis += vv; s_con = fmaf(mse * vv, wp, s_con);
            dx = P0.w - P1.z; dy = P1.x - P1.w; dz = P1.y - P2.x;
            mse = fmaf(dx, dx, fmaf(dy, dy, dz * dz)); vv = V.y * V.z;
            s_vis += vv; s_con = fmaf(mse * vv, wp, s_con);
            dx = P1.z - P2.y; dy = P1.w - P2.z; dz = P2.x - P2.w;
            mse = fmaf(dx, dx, fmaf(dy, dy, dz * dz)); vv = V.z * V.w;
            s_vis += vv; s_con = fmaf(mse * vv, wp, s_con);
        }
    } else {
        for (int p = tid; p < P; p += stride) {
            float wp = w[p];
            const float* np_ = nwa + (size_t)p * C * 3;
            const float* vp_ = vis + (size_t)p * C;
            float px = np_[0], py = np_[1], pz = np_[2], pv = vp_[0];
            for (int i = 1; i < C; i++) {
                float cx = np_[3 * i], cy = np_[3 * i + 1], cz = np_[3 * i + 2];
                float cv = vp_[i];
                float dx = px - cx, dy = py - cy, dz = pz - cz;
                float mse = fmaf(dx, dx, fmaf(dy, dy, dz * dz));
                float vv = pv * cv;
                s_vis += vv;
                s_con = fmaf(mse * vv, wp, s_con);
                px = cx; py = cy; pz = cz; pv = cv;
            }
        }
    }

    __shared__ float shred[9];
    if (threadIdx.x < 9) shred[threadIdx.x] = 0.f;
    __syncthreads();
    float vals[9] = {s_mask, s_nsq, s_den, s_num, s_bce, s_eik, s_sdf, s_con, s_vis};
    #pragma unroll
    for (int k = 0; k < 9; k++) {
        float r = warpSum(vals[k]);
        if ((threadIdx.x & 31) == 0) atomicAdd(&shred[k], r);
    }
    __syncthreads();
    if (threadIdx.x < 9) atomicAdd(&g_acc[threadIdx.x], (double)shred[threadIdx.x]);
}

// ---------------------------------------------------------------------------
// Pass 2: depth |vg*scale - vp| + chamfer sqrt-sum + last-block finalize.
// Also resets g_min / g_acc / g_done for the next graph replay.
// ---------------------------------------------------------------------------
__global__ void __launch_bounds__(256) kP2(
    const float* __restrict__ dpred, const float* __restrict__ dgt,
    const float* __restrict__ mask, float* __restrict__ out, int out_size, int N)
{
    const float den = (float)g_acc[2];
    const float num = (float)g_acc[3];
    float scale = num / den;
    if (!isfinite(scale)) scale = 1.0f;

    const int tid = blockIdx.x * 256 + threadIdx.x;
    const int stride = NP2 * 256;

    const float4* __restrict__ mk4 = (const float4*)mask;
    const float4* __restrict__ dg4 = (const float4*)dgt;
    const float4* __restrict__ dp4 = (const float4*)dpred;

    float s_derr = 0.f;
    for (int g = tid; g < HW4; g += stride) {
        float4 mk = mk4[g];
        float4 dg = dg4[g], dp = dp4[g];
        float m0 = mk.x > 0.5f ? 1.f : 0.f;
        float m1 = mk.y > 0.5f ? 1.f : 0.f;
        float m2 = mk.z > 0.5f ? 1.f : 0.f;
        float m3 = mk.w > 0.5f ? 1.f : 0.f;
        s_derr += fabsf(fmaf(dg.x * m0, scale, -dp.x * m0));
        s_derr += fabsf(fmaf(dg.y * m1, scale, -dp.y * m1));
        s_derr += fabsf(fmaf(dg.z * m2, scale, -dp.z * m2));
        s_derr += fabsf(fmaf(dg.w * m3, scale, -dp.w * m3));
    }

    float s0 = 0.f, s1 = 0.f;
    for (int s = tid; s < 2 * SPTS; s += stride) {
        float d = sqrtf(__uint_as_float(~g_min[s]));
        g_min[s] = 0u;                       // reset for next replay
        if (s < SPTS) s0 += d; else s1 += d;
    }

    __shared__ float shred[3];
    __shared__ unsigned int s_last;
    if (threadIdx.x < 3) shred[threadIdx.x] = 0.f;
    __syncthreads();
    float vals[3] = {s_derr, s0, s1};
    #pragma unroll
    for (int k = 0; k < 3; k++) {
        float r = warpSum(vals[k]);
        if ((threadIdx.x & 31) == 0) atomicAdd(&shred[k], r);
    }
    __syncthreads();
    if (threadIdx.x < 3) atomicAdd(&g_acc[9 + threadIdx.x], (double)shred[threadIdx.x]);

    // --- last-block finalize ---
    __threadfence();
    __syncthreads();
    if (threadIdx.x == 0) s_last = atomicAdd(&g_done, 1u);
    __syncthreads();
    if (s_last == NP2 - 1 && threadIdx.x == 0) {
        __threadfence();
        float a0 = (float)__ldcg(&g_acc[0]), a1 = (float)__ldcg(&g_acc[1]);
        float a2 = (float)__ldcg(&g_acc[2]);
        float a4 = (float)__ldcg(&g_acc[4]), a5 = (float)__ldcg(&g_acc[5]);
        float a6 = (float)__ldcg(&g_acc[6]), a7 = (float)__ldcg(&g_acc[7]);
        float a8 = (float)__ldcg(&g_acc[8]), a9 = (float)__ldcg(&g_acc[9]);
        float a10 = (float)__ldcg(&g_acc[10]), a11 = (float)__ldcg(&g_acc[11]);

        float mask_sum = a0 + 1e-5f;
        float normal_loss = a1 / mask_sum;
        float depth_loss = a9 / (mask_sum + 1e-8f);
        if (a2 < 1e-10f || !isfinite(depth_loss)) depth_loss = 0.0f;
        float pc = (a10 + a11) * (1.0f / (float)SPTS);
        float bce = a4 * (1.0f / (float)HW);
        float inv_n = 1.0f / (float)N;
        float eik = a5 * inv_n;
        float sdfl = a6 * inv_n;
        float con = (a8 > 0.0f) ? a7 / a8 : 0.0f;
        float loss = normal_loss + depth_loss + pc + bce + eik + sdfl + con;
        for (int i = 0; i < out_size; i++) out[i] = loss;

        #pragma unroll
        for (int k = 0; k < 12; k++) g_acc[k] = 0.0;   // reset for next replay
        g_done = 0u;
    }
}

extern "C" void kernel_launch(void* const* d_in, const int* in_sizes, int n_in,
                              void* d_out, int out_size)
{
    const float* npred = (const float*)d_in[0];
    const float* ngt   = (const float*)d_in[1];
    const float* dpred = (const float*)d_in[2];
    const float* dgt   = (const float*)d_in[3];
    const float* X     = (const float*)d_in[4];
    const float* Y     = (const float*)d_in[5];
    const float* mask  = (const float*)d_in[6];
    const float* comp  = (const float*)d_in[7];
    const float* grad  = (const float*)d_in[8];
    const float* sdf   = (const float*)d_in[9];
    const float* nwa   = (const float*)d_in[10];
    const float* vis   = (const float*)d_in[11];
    const float* w     = (const float*)d_in[12];

    int N = in_sizes[9];
    int P = in_sizes[12];
    int C = in_sizes[11] / P;

    // One-time handle creation (host-side only; no device memory).
    static cudaStream_t s2 = nullptr;
    static cudaEvent_t evF = nullptr, evJ = nullptr;
    if (!s2) {
        cudaStreamCreateWithFlags(&s2, cudaStreamNonBlocking);
        cudaEventCreateWithFlags(&evF, cudaEventDisableTiming);
        cudaEventCreateWithFlags(&evJ, cudaEventDisableTiming);
    }

    // Fork: kCham on s2 concurrent with kMain on the main stream; join before kP2.
    cudaEventRecord(evF, 0);
    cudaStreamWaitEvent(s2, evF, 0);
    kCham<<<NCH, CTHR, 0, s2>>>(X, Y);
    cudaEventRecord(evJ, s2);

    kMain<<<NMAIN, 256>>>(npred, ngt, dpred, dgt, mask, comp, grad, sdf, nwa, vis, w, N, P, C);

    cudaStreamWaitEvent(0, evJ, 0);
    kP2<<<NP2, 256>>>(dpred, dgt, mask, (float*)d_out, out_size, N);
}